// round 3
// baseline (speedup 1.0000x reference)
#include <cuda_runtime.h>
#include <cstdint>
#include <cstddef>

typedef unsigned long long ull;

#define SLICES 96
#define NN 250
#define NP 256
#define SROW 256                 // padded rows per slice in g_S
#define SEG 18000000ULL          // 96*250*750 elements per output segment

// Scratch (device globals; zero-initialized at module load, padding rows stay 0)
__device__ __align__(16) float g_V[SLICES * NN * 64];        // nodevec
__device__ __align__(16) float g_S[(size_t)SLICES * SROW * NP]; // relu(V V^T), rows+cols padded to 256
__device__ float g_part[SLICES * 4 * NP];                    // per-jtile row partial sums
__device__ float g_a[SLICES * NP];
__device__ float g_c[SLICES * NP];
__device__ float g_gv[SLICES * NP];

// symmetric tile pairs (i0t <= j0t), 10 of 16
__constant__ int c_ti[10] = {0,0,0,0,1,1,1,2,2,3};
__constant__ int c_tj[10] = {0,1,2,3,1,2,3,2,3,3};

// ---------- f32x2 helpers ----------
__device__ __forceinline__ ull pack2(float x) {
    ull r; asm("mov.b64 %0, {%1, %1};" : "=l"(r) : "f"(x)); return r;
}
__device__ __forceinline__ void fma2(ull& d, ull a, ull b) {
    asm("fma.rn.f32x2 %0, %1, %2, %0;" : "+l"(d) : "l"(a), "l"(b));
}
__device__ __forceinline__ float2 unpack2(ull v) {
    float2 f; asm("mov.b64 {%0, %1}, %2;" : "=f"(f.x), "=f"(f.y) : "l"(v)); return f;
}

// ---------- K1: nodevec = tanh(concat(X) @ W + b), f32x2 ----------
// block: 16 rows, 256 threads = 32 col-pairs x 8 row-groups (rows rg, rg+8)
__global__ void __launch_bounds__(256) k_embed(
    const float* __restrict__ hist, const float* __restrict__ prior,
    const float* __restrict__ obs, const float* __restrict__ W,
    const float* __restrict__ bias)
{
    __shared__ ull Xd[16][224];      // dup-packed X rows  (28672 B)
    __shared__ ull Ws[64 * 32];      // W chunk, natural pairs (16384 B)
    int tid = threadIdx.x;
    int row0 = blockIdx.x * 16;

    // stage X dup-packed (once)
    for (int t = tid; t < 16 * 224; t += 256) {
        int r = t / 224, k = t - r * 224;
        int g = row0 + r;
        float v;
        if (k < 128)      v = hist [g * 128 + k];
        else if (k < 192) v = prior[g * 64  + (k - 128)];
        else              v = obs  [g * 32  + (k - 192)];
        Xd[r][k] = pack2(v);
    }

    int cp = tid & 31, rg = tid >> 5;
    ull acc0 = 0ULL, acc1 = 0ULL;
    const ull* Wg = (const ull*)W;   // [224][32] pairs

    for (int k0 = 0; k0 < 224; k0 += 64) {
        int kn = (224 - k0 < 64) ? (224 - k0) : 64;
        __syncthreads();
        for (int t = tid; t < kn * 32; t += 256) Ws[t] = Wg[(size_t)k0 * 32 + t];
        __syncthreads();
#pragma unroll 8
        for (int k = 0; k < kn; k++) {
            ull w = Ws[k * 32 + cp];
            fma2(acc0, Xd[rg][k0 + k], w);
            fma2(acc1, Xd[rg + 8][k0 + k], w);
        }
    }

    float2 b2 = *(const float2*)&bias[cp * 2];
    float2 r0 = unpack2(acc0), r1 = unpack2(acc1);
    float2 o0 = { tanhf(r0.x + b2.x), tanhf(r0.y + b2.y) };
    float2 o1 = { tanhf(r1.x + b2.x), tanhf(r1.y + b2.y) };
    *(float2*)&g_V[(size_t)(row0 + rg)     * 64 + cp * 2] = o0;
    *(float2*)&g_V[(size_t)(row0 + rg + 8) * 64 + cp * 2] = o1;
}

// ---------- K2: S = relu(V V^T) + per-jtile row sums, f32x2 ----------
__global__ void __launch_bounds__(256) k_sim()
{
    __shared__ float As[32][66];   // As[k][i]  (8448 B)
    __shared__ ull  Bsp[32][65];   // dup-packed, q-interleaved: idx = (j&3)*16 + (j>>2)  (16640 B)
    int slice = blockIdx.z;
    int i0 = blockIdx.y * 64, j0 = blockIdx.x * 64;
    int tx = threadIdx.x, ty = threadIdx.y;
    int tid = ty * 16 + tx;
    const float* Vb = g_V + (size_t)slice * NN * 64;

    ull acc[2][4];
#pragma unroll
    for (int p = 0; p < 2; p++)
#pragma unroll
        for (int q = 0; q < 4; q++) acc[p][q] = 0ULL;

    for (int k0 = 0; k0 < 64; k0 += 32) {
        __syncthreads();
        for (int t = tid; t < 2048; t += 256) {
            int rr = t >> 5, k = t & 31;
            int i = i0 + rr;
            As[k][rr] = (i < NN) ? Vb[(size_t)i * 64 + k0 + k] : 0.f;
            int j = j0 + rr;
            float bv = (j < NN) ? Vb[(size_t)j * 64 + k0 + k] : 0.f;
            Bsp[k][((rr & 3) << 4) | (rr >> 2)] = pack2(bv);
        }
        __syncthreads();
#pragma unroll 8
        for (int k = 0; k < 32; k++) {
            ull a0 = *(const ull*)&As[k][ty * 4];
            ull a1 = *(const ull*)&As[k][ty * 4 + 2];
            ull b0 = Bsp[k][tx];
            ull b1 = Bsp[k][16 + tx];
            ull b2 = Bsp[k][32 + tx];
            ull b3 = Bsp[k][48 + tx];
            fma2(acc[0][0], a0, b0); fma2(acc[0][1], a0, b1);
            fma2(acc[0][2], a0, b2); fma2(acc[0][3], a0, b3);
            fma2(acc[1][0], a1, b0); fma2(acc[1][1], a1, b1);
            fma2(acc[1][2], a1, b2); fma2(acc[1][3], a1, b3);
        }
    }

    // epilogue: relu, store S (padded rows/cols get zeros), row partials
    float m[4][4];
#pragma unroll
    for (int p = 0; p < 2; p++)
#pragma unroll
        for (int q = 0; q < 4; q++) {
            float2 f = unpack2(acc[p][q]);
            m[2 * p][q]     = fmaxf(f.x, 0.f);
            m[2 * p + 1][q] = fmaxf(f.y, 0.f);
        }
    float* Sb = g_S + (size_t)slice * SROW * NP;
    int jb = j0 + tx * 4;
#pragma unroll
    for (int r = 0; r < 4; r++) {
        int i = i0 + ty * 4 + r;
        float4 v = make_float4(m[r][0], m[r][1], m[r][2], m[r][3]);
        *(float4*)&Sb[(size_t)i * NP + jb] = v;
        float rs = v.x + v.y + v.z + v.w;
        rs += __shfl_xor_sync(0xffffffffu, rs, 8);
        rs += __shfl_xor_sync(0xffffffffu, rs, 4);
        rs += __shfl_xor_sync(0xffffffffu, rs, 2);
        rs += __shfl_xor_sync(0xffffffffu, rs, 1);
        if (tx == 0) g_part[(slice * 4 + blockIdx.x) * NP + i] = rs;
    }
}

// ---------- K3: scalars a = d, c = d/r, g = d^2/r ----------
__global__ void __launch_bounds__(256) k_scal()
{
    int slice = blockIdx.x;
    int i = threadIdx.x;
    __shared__ float ds[NP];
    float d = 0.f;
    if (i < NN) {
        const float* p = g_part + slice * 4 * NP;
        float s = p[i] + p[NP + i] + p[2 * NP + i] + p[3 * NP + i];
        d = rsqrtf(s + 1e-9f);
    }
    ds[i] = d;
    __syncthreads();
    float a = 0.f, c = 0.f, gv = 0.f;
    if (i < NN) {
        const float* Srow = g_S + ((size_t)slice * SROW + i) * NP;
        float t = 0.f;
#pragma unroll 4
        for (int j = 0; j < 248; j += 4) {
            float4 v = *reinterpret_cast<const float4*>(Srow + j);
            t = fmaf(v.x, ds[j],     t);
            t = fmaf(v.y, ds[j + 1], t);
            t = fmaf(v.z, ds[j + 2], t);
            t = fmaf(v.w, ds[j + 3], t);
        }
        t = fmaf(Srow[248], ds[248], t);
        t = fmaf(Srow[249], ds[249], t);
        float r = d * t + 1e-9f;
        a = d; c = d / r; gv = d * c;
    }
    g_a[slice * NP + i] = a;
    g_c[slice * NP + i] = c;
    g_gv[slice * NP + i] = gv;
}

// ---------- K4: order-1 outputs -> seg0, seg2 ----------
__global__ void __launch_bounds__(256) k_out1(float* __restrict__ out)
{
    int slice = blockIdx.y;
    int n = blockIdx.x * 2 + (threadIdx.x >> 7);
    int m = (threadIdx.x & 127) * 2;
    if (m >= NN) return;
    float an = g_a[slice * NP + n];
    float2 s  = *reinterpret_cast<const float2*>(g_S + ((size_t)slice * SROW + n) * NP + m);
    float2 cc = *reinterpret_cast<const float2*>(g_c + slice * NP + m);
    float2 v;
    v.x = (m     == n) ? 0.f : an * s.x * cc.x;
    v.y = (m + 1 == n) ? 0.f : an * s.y * cc.y;
    size_t base = ((size_t)(slice * NN + n)) * 750;
    float* o0 = out + base;
    float* o2 = out + 2 * SEG + base;
#pragma unroll
    for (int kt = 0; kt < 3; kt++) {
        *reinterpret_cast<float2*>(o0 + kt * 250 + m) = v;
        *reinterpret_cast<float2*>(o2 + kt * 250 + m) = v;
    }
}

// ---------- K5: M = S diag(g) S (symmetric, f32x2) + order-2 outputs -> seg1, seg3 ----------
__global__ void __launch_bounds__(256) k_gemm2(float* __restrict__ out)
{
    __shared__ float As[32][66];   // As[k][i] = S[i0+i][k0+k]
    __shared__ ull  Bsp[32][65];   // dup(g[k]*S[j0+j][k0+k]), idx = (j&3)*16 + (j>>2)
    int slice = blockIdx.y;
    int i0 = c_ti[blockIdx.x] * 64, j0 = c_tj[blockIdx.x] * 64;
    bool diag = (i0 == j0);
    int tx = threadIdx.x, ty = threadIdx.y;
    int tid = ty * 16 + tx;
    const float* Sb = g_S + (size_t)slice * SROW * NP;
    const float* gg = g_gv + slice * NP;

    ull acc[2][4];
#pragma unroll
    for (int p = 0; p < 2; p++)
#pragma unroll
        for (int q = 0; q < 4; q++) acc[p][q] = 0ULL;

    for (int k0 = 0; k0 < NP; k0 += 32) {   // padding: g=0 and S rows>=250 are zero
        __syncthreads();
        for (int t = tid; t < 2048; t += 256) {
            int rr = t >> 5, k = t & 31;
            As[k][rr] = Sb[(size_t)(i0 + rr) * NP + k0 + k];
            float bv = gg[k0 + k] * Sb[(size_t)(j0 + rr) * NP + k0 + k];
            Bsp[k][((rr & 3) << 4) | (rr >> 2)] = pack2(bv);
        }
        __syncthreads();
#pragma unroll 8
        for (int k = 0; k < 32; k++) {
            ull a0 = *(const ull*)&As[k][ty * 4];
            ull a1 = *(const ull*)&As[k][ty * 4 + 2];
            ull b0 = Bsp[k][tx];
            ull b1 = Bsp[k][16 + tx];
            ull b2 = Bsp[k][32 + tx];
            ull b3 = Bsp[k][48 + tx];
            fma2(acc[0][0], a0, b0); fma2(acc[0][1], a0, b1);
            fma2(acc[0][2], a0, b2); fma2(acc[0][3], a0, b3);
            fma2(acc[1][0], a1, b0); fma2(acc[1][1], a1, b1);
            fma2(acc[1][2], a1, b2); fma2(acc[1][3], a1, b3);
        }
    }

    // unpack M tile
    float m[4][4];   // m[r][q] = M[i0+ty*4+r][j0+tx*4+q]
#pragma unroll
    for (int p = 0; p < 2; p++)
#pragma unroll
        for (int q = 0; q < 4; q++) {
            float2 f = unpack2(acc[p][q]);
            m[2 * p][q] = f.x;
            m[2 * p + 1][q] = f.y;
        }

    int soff = slice * NP;
    int ib = i0 + ty * 4, jb = j0 + tx * 4;
    float2 cj0 = *(const float2*)&g_c[soff + jb];
    float2 cj1 = *(const float2*)&g_c[soff + jb + 2];

    // normal-orientation writes: P'[i][j] = a_i * M[i][j] * c_j
    bool w0ok = (jb < NN), w1ok = (jb + 2 < NN);
#pragma unroll
    for (int r = 0; r < 4; r++) {
        int i = ib + r;
        if (i >= NN) continue;   // only possible in diag tile i0=192
        float ai = g_a[soff + i];
        float v0 = ai * m[r][0] * cj0.x;
        float v1 = ai * m[r][1] * cj0.y;
        float v2 = ai * m[r][2] * cj1.x;
        float v3 = ai * m[r][3] * cj1.y;
        if (diag) {
            if (i == jb)     v0 = 0.f;
            if (i == jb + 1) v1 = 0.f;
            if (i == jb + 2) v2 = 0.f;
            if (i == jb + 3) v3 = 0.f;
        }
        float2 w0 = make_float2(v0, v1), w1 = make_float2(v2, v3);
        size_t base = ((size_t)(slice * NN + i)) * 750;
        float* o1 = out + SEG + base;
        float* o3 = out + 3 * SEG + base;
#pragma unroll
        for (int kt = 0; kt < 3; kt++) {
            if (w0ok) {
                *(float2*)(o1 + kt * 250 + jb) = w0;
                *(float2*)(o3 + kt * 250 + jb) = w0;
            }
            if (w1ok) {
                *(float2*)(o1 + kt * 250 + jb + 2) = w1;
                *(float2*)(o3 + kt * 250 + jb + 2) = w1;
            }
        }
    }

    // transposed-block writes (off-diag only): P'[j][i] = a_j * M[i][j] * c_i
    if (!diag) {
        float2 ci0 = *(const float2*)&g_c[soff + ib];
        float2 ci1 = *(const float2*)&g_c[soff + ib + 2];
#pragma unroll
        for (int q = 0; q < 4; q++) {
            int j = jb + q;
            if (j >= NN) continue;
            float aj = g_a[soff + j];
            float2 t0 = make_float2(aj * m[0][q] * ci0.x, aj * m[1][q] * ci0.y);
            float2 t1 = make_float2(aj * m[2][q] * ci1.x, aj * m[3][q] * ci1.y);
            size_t base = ((size_t)(slice * NN + j)) * 750;
            float* o1 = out + SEG + base;
            float* o3 = out + 3 * SEG + base;
#pragma unroll
            for (int kt = 0; kt < 3; kt++) {
                *(float2*)(o1 + kt * 250 + ib) = t0;
                *(float2*)(o3 + kt * 250 + ib) = t0;
                *(float2*)(o1 + kt * 250 + ib + 2) = t1;
                *(float2*)(o3 + kt * 250 + ib + 2) = t1;
            }
        }
    }
}

extern "C" void kernel_launch(void* const* d_in, const int* in_sizes, int n_in,
                              void* d_out, int out_size)
{
    const float* hist  = (const float*)d_in[0];
    const float* prior = (const float*)d_in[1];
    const float* obs   = (const float*)d_in[2];
    const float* W     = (const float*)d_in[3];
    const float* bias  = (const float*)d_in[4];
    float* out = (float*)d_out;

    k_embed<<<1500, 256>>>(hist, prior, obs, W, bias);
    k_sim  <<<dim3(4, 4, SLICES), dim3(16, 16)>>>();
    k_scal <<<SLICES, 256>>>();
    k_out1 <<<dim3(125, SLICES), 256>>>(out);
    k_gemm2<<<dim3(10, SLICES), dim3(16, 16)>>>(out);
}

// round 5
// speedup vs baseline: 1.0171x; 1.0171x over previous
#include <cuda_runtime.h>
#include <cstdint>
#include <cstddef>

typedef unsigned long long ull;

#define SLICES 96
#define NN 250
#define NP 256
#define SROW 256                 // padded rows per slice in g_S / g_P2
#define SEG 18000000ULL          // 96*250*750 elements per output segment

// Scratch (device globals; zero-initialized at module load, padding stays 0)
__device__ __align__(16) float g_V[SLICES * NN * 64];
__device__ __align__(16) float g_S[(size_t)SLICES * SROW * NP];   // relu(V V^T)
__device__ __align__(16) float g_P2[(size_t)SLICES * SROW * NP];  // scaled+masked order-2 P
__device__ float g_part[SLICES * 4 * NP];
__device__ float g_a[SLICES * NP];
__device__ float g_c[SLICES * NP];
__device__ float g_gv[SLICES * NP];

// symmetric tile pairs (i0t <= j0t), 10 of 16
__constant__ int c_ti[10] = {0,0,0,0,1,1,1,2,2,3};
__constant__ int c_tj[10] = {0,1,2,3,1,2,3,2,3,3};

// ---------- f32x2 helpers ----------
__device__ __forceinline__ ull pack2(float x) {
    ull r; asm("mov.b64 %0, {%1, %1};" : "=l"(r) : "f"(x)); return r;
}
__device__ __forceinline__ void fma2(ull& d, ull a, ull b) {
    asm("fma.rn.f32x2 %0, %1, %2, %0;" : "+l"(d) : "l"(a), "l"(b));
}
__device__ __forceinline__ float2 unpack2(ull v) {
    float2 f; asm("mov.b64 {%0, %1}, %2;" : "=f"(f.x), "=f"(f.y) : "l"(v)); return f;
}

// ---------- K1: nodevec = tanh(concat(X) @ W + b), f32x2 ----------
__global__ void __launch_bounds__(256) k_embed(
    const float* __restrict__ hist, const float* __restrict__ prior,
    const float* __restrict__ obs, const float* __restrict__ W,
    const float* __restrict__ bias)
{
    __shared__ ull Xd[16][224];
    __shared__ ull Ws[64 * 32];
    int tid = threadIdx.x;
    int row0 = blockIdx.x * 16;

    for (int t = tid; t < 16 * 224; t += 256) {
        int r = t / 224, k = t - r * 224;
        int g = row0 + r;
        float v;
        if (k < 128)      v = hist [g * 128 + k];
        else if (k < 192) v = prior[g * 64  + (k - 128)];
        else              v = obs  [g * 32  + (k - 192)];
        Xd[r][k] = pack2(v);
    }

    int cp = tid & 31, rg = tid >> 5;
    ull acc0 = 0ULL, acc1 = 0ULL;
    const ull* Wg = (const ull*)W;

    for (int k0 = 0; k0 < 224; k0 += 64) {
        int kn = (224 - k0 < 64) ? (224 - k0) : 64;
        __syncthreads();
        for (int t = tid; t < kn * 32; t += 256) Ws[t] = Wg[(size_t)k0 * 32 + t];
        __syncthreads();
#pragma unroll 8
        for (int k = 0; k < kn; k++) {
            ull w = Ws[k * 32 + cp];
            fma2(acc0, Xd[rg][k0 + k], w);
            fma2(acc1, Xd[rg + 8][k0 + k], w);
        }
    }

    float2 b2 = *(const float2*)&bias[cp * 2];
    float2 r0 = unpack2(acc0), r1 = unpack2(acc1);
    float2 o0 = { tanhf(r0.x + b2.x), tanhf(r0.y + b2.y) };
    float2 o1 = { tanhf(r1.x + b2.x), tanhf(r1.y + b2.y) };
    *(float2*)&g_V[(size_t)(row0 + rg)     * 64 + cp * 2] = o0;
    *(float2*)&g_V[(size_t)(row0 + rg + 8) * 64 + cp * 2] = o1;
}

// ---------- K2: S = relu(V V^T) + per-jtile row sums ----------
__global__ void __launch_bounds__(256) k_sim()
{
    __shared__ float As[32][66];
    __shared__ ull  Bsp[32][65];
    int slice = blockIdx.z;
    int i0 = blockIdx.y * 64, j0 = blockIdx.x * 64;
    int tx = threadIdx.x, ty = threadIdx.y;
    int tid = ty * 16 + tx;
    const float* Vb = g_V + (size_t)slice * NN * 64;

    ull acc[2][4];
#pragma unroll
    for (int p = 0; p < 2; p++)
#pragma unroll
        for (int q = 0; q < 4; q++) acc[p][q] = 0ULL;

    for (int k0 = 0; k0 < 64; k0 += 32) {
        __syncthreads();
        for (int t = tid; t < 2048; t += 256) {
            int rr = t >> 5, k = t & 31;
            int i = i0 + rr;
            As[k][rr] = (i < NN) ? Vb[(size_t)i * 64 + k0 + k] : 0.f;
            int j = j0 + rr;
            float bv = (j < NN) ? Vb[(size_t)j * 64 + k0 + k] : 0.f;
            Bsp[k][((rr & 3) << 4) | (rr >> 2)] = pack2(bv);
        }
        __syncthreads();
#pragma unroll 8
        for (int k = 0; k < 32; k++) {
            ull a0 = *(const ull*)&As[k][ty * 4];
            ull a1 = *(const ull*)&As[k][ty * 4 + 2];
            ull b0 = Bsp[k][tx];
            ull b1 = Bsp[k][16 + tx];
            ull b2 = Bsp[k][32 + tx];
            ull b3 = Bsp[k][48 + tx];
            fma2(acc[0][0], a0, b0); fma2(acc[0][1], a0, b1);
            fma2(acc[0][2], a0, b2); fma2(acc[0][3], a0, b3);
            fma2(acc[1][0], a1, b0); fma2(acc[1][1], a1, b1);
            fma2(acc[1][2], a1, b2); fma2(acc[1][3], a1, b3);
        }
    }

    float m[4][4];
#pragma unroll
    for (int p = 0; p < 2; p++)
#pragma unroll
        for (int q = 0; q < 4; q++) {
            float2 f = unpack2(acc[p][q]);
            m[2 * p][q]     = fmaxf(f.x, 0.f);
            m[2 * p + 1][q] = fmaxf(f.y, 0.f);
        }
    float* Sb = g_S + (size_t)slice * SROW * NP;
    int jb = j0 + tx * 4;
#pragma unroll
    for (int r = 0; r < 4; r++) {
        int i = i0 + ty * 4 + r;
        float4 v = make_float4(m[r][0], m[r][1], m[r][2], m[r][3]);
        *(float4*)&Sb[(size_t)i * NP + jb] = v;
        float rs = v.x + v.y + v.z + v.w;
        rs += __shfl_xor_sync(0xffffffffu, rs, 8);
        rs += __shfl_xor_sync(0xffffffffu, rs, 4);
        rs += __shfl_xor_sync(0xffffffffu, rs, 2);
        rs += __shfl_xor_sync(0xffffffffu, rs, 1);
        if (tx == 0) g_part[(slice * 4 + blockIdx.x) * NP + i] = rs;
    }
}

// ---------- K3: scalars a = d, c = d/r, g = d^2/r ----------
__global__ void __launch_bounds__(256) k_scal()
{
    int slice = blockIdx.x;
    int i = threadIdx.x;
    __shared__ float ds[NP];
    float d = 0.f;
    if (i < NN) {
        const float* p = g_part + slice * 4 * NP;
        float s = p[i] + p[NP + i] + p[2 * NP + i] + p[3 * NP + i];
        d = rsqrtf(s + 1e-9f);
    }
    ds[i] = d;
    __syncthreads();
    float a = 0.f, c = 0.f, gv = 0.f;
    if (i < NN) {
        const float* Srow = g_S + ((size_t)slice * SROW + i) * NP;
        float t = 0.f;
#pragma unroll 4
        for (int j = 0; j < 248; j += 4) {
            float4 v = *reinterpret_cast<const float4*>(Srow + j);
            t = fmaf(v.x, ds[j],     t);
            t = fmaf(v.y, ds[j + 1], t);
            t = fmaf(v.z, ds[j + 2], t);
            t = fmaf(v.w, ds[j + 3], t);
        }
        t = fmaf(Srow[248], ds[248], t);
        t = fmaf(Srow[249], ds[249], t);
        float r = d * t + 1e-9f;
        a = d; c = d / r; gv = d * c;
    }
    g_a[slice * NP + i] = a;
    g_c[slice * NP + i] = c;
    g_gv[slice * NP + i] = gv;
}

// ---------- K4: order-1 outputs -> seg0, seg2 ----------
__global__ void __launch_bounds__(256) k_out1(float* __restrict__ out)
{
    int slice = blockIdx.y;
    int n = blockIdx.x * 2 + (threadIdx.x >> 7);
    int m = (threadIdx.x & 127) * 2;
    if (m >= NN) return;
    float an = g_a[slice * NP + n];
    float2 s  = *reinterpret_cast<const float2*>(g_S + ((size_t)slice * SROW + n) * NP + m);
    float2 cc = *reinterpret_cast<const float2*>(g_c + slice * NP + m);
    float2 v;
    v.x = (m     == n) ? 0.f : an * s.x * cc.x;
    v.y = (m + 1 == n) ? 0.f : an * s.y * cc.y;
    size_t base = ((size_t)(slice * NN + n)) * 750;
    float* o0 = out + base;
    float* o2 = out + 2 * SEG + base;
#pragma unroll
    for (int kt = 0; kt < 3; kt++) {
        *reinterpret_cast<float2*>(o0 + kt * 250 + m) = v;
        *reinterpret_cast<float2*>(o2 + kt * 250 + m) = v;
    }
}

// ---------- K5: M = S diag(g) S (symmetric) -> g_P2 scaled+masked, coalesced only ----------
__global__ void __launch_bounds__(256) k_gemm2()
{
    __shared__ float As[32][66];
    __shared__ __align__(16) ull Bsp[32][68];  // 17408 B; also backs Ts[64][68]
    float (*Ts)[68] = (float(*)[68])Bsp;       // row stride 272 B (16B-aligned)
    int slice = blockIdx.y;
    int i0 = c_ti[blockIdx.x] * 64, j0 = c_tj[blockIdx.x] * 64;
    bool diag = (i0 == j0);
    int tx = threadIdx.x, ty = threadIdx.y;
    int tid = ty * 16 + tx;
    const float* Sb = g_S + (size_t)slice * SROW * NP;
    const float* gg = g_gv + slice * NP;
    float* P2b = g_P2 + (size_t)slice * SROW * NP;

    ull acc[2][4];
#pragma unroll
    for (int p = 0; p < 2; p++)
#pragma unroll
        for (int q = 0; q < 4; q++) acc[p][q] = 0ULL;

    for (int k0 = 0; k0 < NP; k0 += 32) {   // padding rows/g are zero
        __syncthreads();
        for (int t = tid; t < 2048; t += 256) {
            int rr = t >> 5, k = t & 31;
            As[k][rr] = Sb[(size_t)(i0 + rr) * NP + k0 + k];
            float bv = gg[k0 + k] * Sb[(size_t)(j0 + rr) * NP + k0 + k];
            Bsp[k][((rr & 3) << 4) | (rr >> 2)] = pack2(bv);
        }
        __syncthreads();
#pragma unroll 8
        for (int k = 0; k < 32; k++) {
            ull a0 = *(const ull*)&As[k][ty * 4];
            ull a1 = *(const ull*)&As[k][ty * 4 + 2];
            ull b0 = Bsp[k][tx];
            ull b1 = Bsp[k][16 + tx];
            ull b2 = Bsp[k][32 + tx];
            ull b3 = Bsp[k][48 + tx];
            fma2(acc[0][0], a0, b0); fma2(acc[0][1], a0, b1);
            fma2(acc[0][2], a0, b2); fma2(acc[0][3], a0, b3);
            fma2(acc[1][0], a1, b0); fma2(acc[1][1], a1, b1);
            fma2(acc[1][2], a1, b2); fma2(acc[1][3], a1, b3);
        }
    }

    float m[4][4];   // m[r][q] = M[i0+ty*4+r][j0+tx*4+q]
#pragma unroll
    for (int p = 0; p < 2; p++)
#pragma unroll
        for (int q = 0; q < 4; q++) {
            float2 f = unpack2(acc[p][q]);
            m[2 * p][q] = f.x;
            m[2 * p + 1][q] = f.y;
        }

    int soff = slice * NP;
    int ib = i0 + ty * 4, jb = j0 + tx * 4;
    float4 cj = *(const float4*)&g_c[soff + jb];
    float4 ai4 = *(const float4*)&g_a[soff + ib];
    float aiv[4] = {ai4.x, ai4.y, ai4.z, ai4.w};

    // normal orientation into scratch: P2'[i][j] = a_i * M[i][j] * c_j  (coalesced STG.128)
#pragma unroll
    for (int r = 0; r < 4; r++) {
        int i = ib + r;
        float ai = aiv[r];
        float4 w;
        w.x = ai * m[r][0] * cj.x;
        w.y = ai * m[r][1] * cj.y;
        w.z = ai * m[r][2] * cj.z;
        w.w = ai * m[r][3] * cj.w;
        if (diag) {
            if (i == jb)     w.x = 0.f;
            if (i == jb + 1) w.y = 0.f;
            if (i == jb + 2) w.z = 0.f;
            if (i == jb + 3) w.w = 0.f;
        }
        *(float4*)&P2b[(size_t)i * NP + jb] = w;
    }

    // transposed block via smem transpose (off-diag only): P2'[j][i] = a_j * M[i][j] * c_i
    if (!diag) {
        float4 aj4 = *(const float4*)&g_a[soff + jb];
        float4 ci4 = *(const float4*)&g_c[soff + ib];
        float ajv[4] = {aj4.x, aj4.y, aj4.z, aj4.w};
        float civ[4] = {ci4.x, ci4.y, ci4.z, ci4.w};
        __syncthreads();   // done reading Bsp
#pragma unroll
        for (int q = 0; q < 4; q++)
#pragma unroll
            for (int r = 0; r < 4; r++)
                Ts[tx * 4 + q][ty * 4 + r] = ajv[q] * m[r][q] * civ[r];
        __syncthreads();
        int row = tid >> 2, c0 = (tid & 3) * 16;
#pragma unroll
        for (int u = 0; u < 4; u++) {
            float4 v = *(const float4*)&Ts[row][c0 + u * 4];
            *(float4*)&P2b[(size_t)(j0 + row) * NP + i0 + c0 + u * 4] = v;
        }
    }
}

// ---------- K6: order-2 outputs -> seg1, seg3 (pure coalesced stream) ----------
__global__ void __launch_bounds__(256) k_out2(float* __restrict__ out)
{
    int slice = blockIdx.y;
    int n = blockIdx.x * 2 + (threadIdx.x >> 7);
    int m = (threadIdx.x & 127) * 2;
    if (m >= NN) return;
    float2 v = *reinterpret_cast<const float2*>(g_P2 + ((size_t)slice * SROW + n) * NP + m);
    size_t base = ((size_t)(slice * NN + n)) * 750;
    float* o1 = out + SEG + base;
    float* o3 = out + 3 * SEG + base;
#pragma unroll
    for (int kt = 0; kt < 3; kt++) {
        *reinterpret_cast<float2*>(o1 + kt * 250 + m) = v;
        *reinterpret_cast<float2*>(o3 + kt * 250 + m) = v;
    }
}

extern "C" void kernel_launch(void* const* d_in, const int* in_sizes, int n_in,
                              void* d_out, int out_size)
{
    const float* hist  = (const float*)d_in[0];
    const float* prior = (const float*)d_in[1];
    const float* obs   = (const float*)d_in[2];
    const float* W     = (const float*)d_in[3];
    const float* bias  = (const float*)d_in[4];
    float* out = (float*)d_out;

    k_embed<<<1500, 256>>>(hist, prior, obs, W, bias);
    k_sim  <<<dim3(4, 4, SLICES), dim3(16, 16)>>>();
    k_scal <<<SLICES, 256>>>();
    k_out1 <<<dim3(125, SLICES), 256>>>(out);
    k_gemm2<<<dim3(10, SLICES), dim3(16, 16)>>>();
    k_out2 <<<dim3(125, SLICES), 256>>>(out);
}

// round 7
// speedup vs baseline: 1.1655x; 1.1459x over previous
#include <cuda_runtime.h>
#include <cstdint>
#include <cstddef>

typedef unsigned long long ull;

#define SLICES 96
#define NN 250
#define NP 256
#define SROW 256
#define SEG 18000000ULL   // 96*250*750 elements per output segment

// Scratch (device globals; zero-initialized at module load, padding stays 0)
__device__ __align__(16) float g_V[(size_t)SLICES * 256 * 64];    // padded 256 rows/slice
__device__ __align__(16) float g_S[(size_t)SLICES * SROW * NP];   // relu(V V^T)
__device__ __align__(16) float g_P2[(size_t)SLICES * SROW * NP];  // scaled+masked order-2 P
__device__ __align__(16) float g_a[SLICES * NP];
__device__ __align__(16) float g_c[SLICES * NP];
__device__ __align__(16) float g_gv[SLICES * NP];

// symmetric 128-tiles: (0,0),(0,1),(1,1)
__constant__ int c_ti3[3] = {0, 0, 1};
__constant__ int c_tj3[3] = {0, 1, 1};

// ---------- f32x2 helpers ----------
__device__ __forceinline__ ull pack2(float x) {
    ull r; asm("mov.b64 %0, {%1, %1};" : "=l"(r) : "f"(x)); return r;
}
__device__ __forceinline__ void fma2(ull& d, ull a, ull b) {
    asm("fma.rn.f32x2 %0, %1, %2, %0;" : "+l"(d) : "l"(a), "l"(b));
}
__device__ __forceinline__ float2 unpack2(ull v) {
    float2 f; asm("mov.b64 {%0, %1}, %2;" : "=f"(f.x), "=f"(f.y) : "l"(v)); return f;
}

// ---------- K1: nodevec = tanh(concat(X) @ W + b), f32x2 ----------
__global__ void __launch_bounds__(256) k_embed(
    const float* __restrict__ hist, const float* __restrict__ prior,
    const float* __restrict__ obs, const float* __restrict__ W,
    const float* __restrict__ bias)
{
    __shared__ ull Xd[16][224];
    __shared__ ull Ws[64 * 32];
    int tid = threadIdx.x;
    int row0 = blockIdx.x * 16;

    for (int t = tid; t < 16 * 224; t += 256) {
        int r = t / 224, k = t - r * 224;
        int g = row0 + r;
        float v;
        if (k < 128)      v = hist [g * 128 + k];
        else if (k < 192) v = prior[g * 64  + (k - 128)];
        else              v = obs  [g * 32  + (k - 192)];
        Xd[r][k] = pack2(v);
    }

    int cp = tid & 31, rg = tid >> 5;
    ull acc0 = 0ULL, acc1 = 0ULL;
    const ull* Wg = (const ull*)W;

    for (int k0 = 0; k0 < 224; k0 += 64) {
        int kn = (224 - k0 < 64) ? (224 - k0) : 64;
        __syncthreads();
        for (int t = tid; t < kn * 32; t += 256) Ws[t] = Wg[(size_t)k0 * 32 + t];
        __syncthreads();
#pragma unroll 8
        for (int k = 0; k < kn; k++) {
            ull w = Ws[k * 32 + cp];
            fma2(acc0, Xd[rg][k0 + k], w);
            fma2(acc1, Xd[rg + 8][k0 + k], w);
        }
    }

    float2 b2 = *(const float2*)&bias[cp * 2];
    float2 r0 = unpack2(acc0), r1 = unpack2(acc1);
    float2 o0 = { tanhf(r0.x + b2.x), tanhf(r0.y + b2.y) };
    float2 o1 = { tanhf(r1.x + b2.x), tanhf(r1.y + b2.y) };
    // map flat row -> padded (slice*256 + local) layout
    int g0 = row0 + rg;
    int s0 = g0 / 250;
    *(float2*)&g_V[(size_t)(s0 * 256 + g0 - s0 * 250) * 64 + cp * 2] = o0;
    int g1 = row0 + rg + 8;
    int s1 = g1 / 250;
    *(float2*)&g_V[(size_t)(s1 * 256 + g1 - s1 * 250) * 64 + cp * 2] = o1;
}

// ---------- K2: S = relu(V V^T), 128x128 tiles, 8x8/thread, symmetric ----------
__global__ void __launch_bounds__(256, 2) k_sim()
{
    __shared__ __align__(16) ull Asd[16][132];   // dup-packed A rows (128 used)
    __shared__ __align__(16) ull Bsn[16][68];    // natural col-pairs (64 used); float view [16][136]
    int slice = blockIdx.y;
    int ti = c_ti3[blockIdx.x], tj = c_tj3[blockIdx.x];
    int i0 = ti * 128, j0 = tj * 128;
    int tid = threadIdx.x;
    int tx = tid & 15, ty = tid >> 4;
    const float* Vb = g_V + (size_t)slice * 256 * 64;

    ull acc[8][4];
#pragma unroll
    for (int r = 0; r < 8; r++)
#pragma unroll
        for (int q = 0; q < 4; q++) acc[r][q] = 0ULL;

    for (int k0 = 0; k0 < 64; k0 += 16) {
        __syncthreads();
        for (int t = tid; t < 2048; t += 256) {
            int r = t >> 4, k = t & 15;
            float av = Vb[(size_t)(i0 + r) * 64 + k0 + k];
            Asd[k][r] = pack2(av);
            float bv = (ti == tj) ? av : Vb[(size_t)(j0 + r) * 64 + k0 + k];
            ((float(*)[136])Bsn)[k][r] = bv;
        }
        __syncthreads();
#pragma unroll
        for (int k = 0; k < 16; k++) {
            const ulonglong2* ap = (const ulonglong2*)&Asd[k][ty * 8];
            ulonglong2 A01 = ap[0], A23 = ap[1], A45 = ap[2], A67 = ap[3];
            const ulonglong2* bp = (const ulonglong2*)&Bsn[k][tx * 4];
            ulonglong2 B01 = bp[0], B23 = bp[1];
            fma2(acc[0][0], A01.x, B01.x); fma2(acc[0][1], A01.x, B01.y);
            fma2(acc[0][2], A01.x, B23.x); fma2(acc[0][3], A01.x, B23.y);
            fma2(acc[1][0], A01.y, B01.x); fma2(acc[1][1], A01.y, B01.y);
            fma2(acc[1][2], A01.y, B23.x); fma2(acc[1][3], A01.y, B23.y);
            fma2(acc[2][0], A23.x, B01.x); fma2(acc[2][1], A23.x, B01.y);
            fma2(acc[2][2], A23.x, B23.x); fma2(acc[2][3], A23.x, B23.y);
            fma2(acc[3][0], A23.y, B01.x); fma2(acc[3][1], A23.y, B01.y);
            fma2(acc[3][2], A23.y, B23.x); fma2(acc[3][3], A23.y, B23.y);
            fma2(acc[4][0], A45.x, B01.x); fma2(acc[4][1], A45.x, B01.y);
            fma2(acc[4][2], A45.x, B23.x); fma2(acc[4][3], A45.x, B23.y);
            fma2(acc[5][0], A45.y, B01.x); fma2(acc[5][1], A45.y, B01.y);
            fma2(acc[5][2], A45.y, B23.x); fma2(acc[5][3], A45.y, B23.y);
            fma2(acc[6][0], A67.x, B01.x); fma2(acc[6][1], A67.x, B01.y);
            fma2(acc[6][2], A67.x, B23.x); fma2(acc[6][3], A67.x, B23.y);
            fma2(acc[7][0], A67.y, B01.x); fma2(acc[7][1], A67.y, B01.y);
            fma2(acc[7][2], A67.y, B23.x); fma2(acc[7][3], A67.y, B23.y);
        }
    }

    float v[8][8];
#pragma unroll
    for (int r = 0; r < 8; r++)
#pragma unroll
        for (int q = 0; q < 4; q++) {
            float2 f = unpack2(acc[r][q]);
            v[r][2 * q]     = fmaxf(f.x, 0.f);
            v[r][2 * q + 1] = fmaxf(f.y, 0.f);
        }

    float* Sb = g_S + (size_t)slice * SROW * NP;
    int ib = i0 + ty * 8, jb = j0 + tx * 8;
#pragma unroll
    for (int r = 0; r < 8; r++) {
        *(float4*)&Sb[(size_t)(ib + r) * NP + jb]     = make_float4(v[r][0], v[r][1], v[r][2], v[r][3]);
        *(float4*)&Sb[(size_t)(ib + r) * NP + jb + 4] = make_float4(v[r][4], v[r][5], v[r][6], v[r][7]);
    }
    if (ti != tj) {
#pragma unroll
        for (int q = 0; q < 8; q++) {
            *(float4*)&Sb[(size_t)(jb + q) * NP + ib]     = make_float4(v[0][q], v[1][q], v[2][q], v[3][q]);
            *(float4*)&Sb[(size_t)(jb + q) * NP + ib + 4] = make_float4(v[4][q], v[5][q], v[6][q], v[7][q]);
        }
    }
}

// ---------- K3: rowsums + scalars a = d, c = d/r, g = d^2/r ----------
__global__ void __launch_bounds__(256) k_scal()
{
    int slice = blockIdx.x;
    int i = threadIdx.x;
    __shared__ float ds[NP];
    const float* Srow = g_S + ((size_t)slice * SROW + i) * NP;
    float d = 0.f;
    if (i < NN) {
        float s = 0.f;
#pragma unroll 4
        for (int j = 0; j < NP; j += 4) {
            float4 x = *(const float4*)(Srow + j);
            s += x.x + x.y + x.z + x.w;
        }
        d = rsqrtf(s + 1e-9f);
    }
    ds[i] = d;
    __syncthreads();
    float a = 0.f, c = 0.f, gv = 0.f;
    if (i < NN) {
        float t = 0.f;
#pragma unroll 4
        for (int j = 0; j < NP; j += 4) {
            float4 x = *(const float4*)(Srow + j);
            t = fmaf(x.x, ds[j],     t);
            t = fmaf(x.y, ds[j + 1], t);
            t = fmaf(x.z, ds[j + 2], t);
            t = fmaf(x.w, ds[j + 3], t);
        }
        float r = d * t + 1e-9f;
        a = d; c = d / r; gv = d * c;
    }
    g_a[slice * NP + i] = a;
    g_c[slice * NP + i] = c;
    g_gv[slice * NP + i] = gv;
}

// ---------- K4: order-1 outputs -> seg0, seg2 ----------
__global__ void __launch_bounds__(256) k_out1(float* __restrict__ out)
{
    int slice = blockIdx.y;
    int n = blockIdx.x * 2 + (threadIdx.x >> 7);
    int m = (threadIdx.x & 127) * 2;
    if (m >= NN) return;
    float an = g_a[slice * NP + n];
    float2 s  = *reinterpret_cast<const float2*>(g_S + ((size_t)slice * SROW + n) * NP + m);
    float2 cc = *reinterpret_cast<const float2*>(g_c + slice * NP + m);
    float2 v;
    v.x = (m     == n) ? 0.f : an * s.x * cc.x;
    v.y = (m + 1 == n) ? 0.f : an * s.y * cc.y;
    size_t base = ((size_t)(slice * NN + n)) * 750;
    float* o0 = out + base;
    float* o2 = out + 2 * SEG + base;
#pragma unroll
    for (int kt = 0; kt < 3; kt++) {
        *reinterpret_cast<float2*>(o0 + kt * 250 + m) = v;
        *reinterpret_cast<float2*>(o2 + kt * 250 + m) = v;
    }
}

// ---------- K5: M = S diag(g) S, 128x128 tiles, symmetric -> g_P2 scaled+masked ----------
__global__ void __launch_bounds__(256, 2) k_gemm2()
{
    __shared__ __align__(16) ull Asd[16][132];
    __shared__ __align__(16) ull Bsn[16][68];
    int slice = blockIdx.y;
    int ti = c_ti3[blockIdx.x], tj = c_tj3[blockIdx.x];
    int i0 = ti * 128, j0 = tj * 128;
    bool diag = (ti == tj);
    int tid = threadIdx.x;
    int tx = tid & 15, ty = tid >> 4;
    const float* Sb = g_S + (size_t)slice * SROW * NP;
    const float* gg = g_gv + slice * NP;
    float* P2b = g_P2 + (size_t)slice * SROW * NP;

    ull acc[8][4];
#pragma unroll
    for (int r = 0; r < 8; r++)
#pragma unroll
        for (int q = 0; q < 4; q++) acc[r][q] = 0ULL;

    for (int k0 = 0; k0 < NP; k0 += 16) {
        __syncthreads();
        for (int t = tid; t < 2048; t += 256) {
            int r = t >> 4, k = t & 15;
            Asd[k][r] = pack2(Sb[(size_t)(i0 + r) * NP + k0 + k]);
            ((float(*)[136])Bsn)[k][r] = gg[k0 + k] * Sb[(size_t)(j0 + r) * NP + k0 + k];
        }
        __syncthreads();
#pragma unroll
        for (int k = 0; k < 16; k++) {
            const ulonglong2* ap = (const ulonglong2*)&Asd[k][ty * 8];
            ulonglong2 A01 = ap[0], A23 = ap[1], A45 = ap[2], A67 = ap[3];
            const ulonglong2* bp = (const ulonglong2*)&Bsn[k][tx * 4];
            ulonglong2 B01 = bp[0], B23 = bp[1];
            fma2(acc[0][0], A01.x, B01.x); fma2(acc[0][1], A01.x, B01.y);
            fma2(acc[0][2], A01.x, B23.x); fma2(acc[0][3], A01.x, B23.y);
            fma2(acc[1][0], A01.y, B01.x); fma2(acc[1][1], A01.y, B01.y);
            fma2(acc[1][2], A01.y, B23.x); fma2(acc[1][3], A01.y, B23.y);
            fma2(acc[2][0], A23.x, B01.x); fma2(acc[2][1], A23.x, B01.y);
            fma2(acc[2][2], A23.x, B23.x); fma2(acc[2][3], A23.x, B23.y);
            fma2(acc[3][0], A23.y, B01.x); fma2(acc[3][1], A23.y, B01.y);
            fma2(acc[3][2], A23.y, B23.x); fma2(acc[3][3], A23.y, B23.y);
            fma2(acc[4][0], A45.x, B01.x); fma2(acc[4][1], A45.x, B01.y);
            fma2(acc[4][2], A45.x, B23.x); fma2(acc[4][3], A45.x, B23.y);
            fma2(acc[5][0], A45.y, B01.x); fma2(acc[5][1], A45.y, B01.y);
            fma2(acc[5][2], A45.y, B23.x); fma2(acc[5][3], A45.y, B23.y);
            fma2(acc[6][0], A67.x, B01.x); fma2(acc[6][1], A67.x, B01.y);
            fma2(acc[6][2], A67.x, B23.x); fma2(acc[6][3], A67.x, B23.y);
            fma2(acc[7][0], A67.y, B01.x); fma2(acc[7][1], A67.y, B01.y);
            fma2(acc[7][2], A67.y, B23.x); fma2(acc[7][3], A67.y, B23.y);
        }
    }

    float m[8][8];
#pragma unroll
    for (int r = 0; r < 8; r++)
#pragma unroll
        for (int q = 0; q < 4; q++) {
            float2 f = unpack2(acc[r][q]);
            m[r][2 * q] = f.x;
            m[r][2 * q + 1] = f.y;
        }

    int soff = slice * NP;
    int ib = i0 + ty * 8, jb = j0 + tx * 8;
    float4 cjA = *(const float4*)&g_c[soff + jb];
    float4 cjB = *(const float4*)&g_c[soff + jb + 4];
    float4 aiA = *(const float4*)&g_a[soff + ib];
    float4 aiB = *(const float4*)&g_a[soff + ib + 4];
    float aiv[8] = {aiA.x, aiA.y, aiA.z, aiA.w, aiB.x, aiB.y, aiB.z, aiB.w};
    float cjv[8] = {cjA.x, cjA.y, cjA.z, cjA.w, cjB.x, cjB.y, cjB.z, cjB.w};

    if (diag && tx == ty) {
#pragma unroll
        for (int r = 0; r < 8; r++) m[r][r] = 0.f;
    }

    // normal orientation: P2'[i][j] = a_i * M[i][j] * c_j  (coalesced)
#pragma unroll
    for (int r = 0; r < 8; r++) {
        float ai = aiv[r];
        *(float4*)&P2b[(size_t)(ib + r) * NP + jb] =
            make_float4(ai * m[r][0] * cjv[0], ai * m[r][1] * cjv[1],
                        ai * m[r][2] * cjv[2], ai * m[r][3] * cjv[3]);
        *(float4*)&P2b[(size_t)(ib + r) * NP + jb + 4] =
            make_float4(ai * m[r][4] * cjv[4], ai * m[r][5] * cjv[5],
                        ai * m[r][6] * cjv[6], ai * m[r][7] * cjv[7]);
    }

    // transposed block (off-diag only): P2'[j][i] = a_j * M[i][j] * c_i
    if (!diag) {
        float4 ciA = *(const float4*)&g_c[soff + ib];
        float4 ciB = *(const float4*)&g_c[soff + ib + 4];
        float4 ajA = *(const float4*)&g_a[soff + jb];
        float4 ajB = *(const float4*)&g_a[soff + jb + 4];
        float civ[8] = {ciA.x, ciA.y, ciA.z, ciA.w, ciB.x, ciB.y, ciB.z, ciB.w};
        float ajv[8] = {ajA.x, ajA.y, ajA.z, ajA.w, ajB.x, ajB.y, ajB.z, ajB.w};
#pragma unroll
        for (int q = 0; q < 8; q++) {
            float aj = ajv[q];
            *(float4*)&P2b[(size_t)(jb + q) * NP + ib] =
                make_float4(aj * m[0][q] * civ[0], aj * m[1][q] * civ[1],
                            aj * m[2][q] * civ[2], aj * m[3][q] * civ[3]);
            *(float4*)&P2b[(size_t)(jb + q) * NP + ib + 4] =
                make_float4(aj * m[4][q] * civ[4], aj * m[5][q] * civ[5],
                            aj * m[6][q] * civ[6], aj * m[7][q] * civ[7]);
        }
    }
}

// ---------- K6: order-2 outputs -> seg1, seg3 (pure coalesced stream) ----------
__global__ void __launch_bounds__(256) k_out2(float* __restrict__ out)
{
    int slice = blockIdx.y;
    int n = blockIdx.x * 2 + (threadIdx.x >> 7);
    int m = (threadIdx.x & 127) * 2;
    if (m >= NN) return;
    float2 v = *reinterpret_cast<const float2*>(g_P2 + ((size_t)slice * SROW + n) * NP + m);
    size_t base = ((size_t)(slice * NN + n)) * 750;
    float* o1 = out + SEG + base;
    float* o3 = out + 3 * SEG + base;
#pragma unroll
    for (int kt = 0; kt < 3; kt++) {
        *reinterpret_cast<float2*>(o1 + kt * 250 + m) = v;
        *reinterpret_cast<float2*>(o3 + kt * 250 + m) = v;
    }
}

extern "C" void kernel_launch(void* const* d_in, const int* in_sizes, int n_in,
                              void* d_out, int out_size)
{
    const float* hist  = (const float*)d_in[0];
    const float* prior = (const float*)d_in[1];
    const float* obs   = (const float*)d_in[2];
    const float* W     = (const float*)d_in[3];
    const float* bias  = (const float*)d_in[4];
    float* out = (float*)d_out;

    k_embed<<<1500, 256>>>(hist, prior, obs, W, bias);
    k_sim  <<<dim3(3, SLICES), 256>>>();
    k_scal <<<SLICES, 256>>>();
    k_out1 <<<dim3(125, SLICES), 256>>>(out);
    k_gemm2<<<dim3(3, SLICES), 256>>>();
    k_out2 <<<dim3(125, SLICES), 256>>>(out);
}